// round 3
// baseline (speedup 1.0000x reference)
#include <cuda_runtime.h>
#include <cstdint>

// Problem constants (fixed by the reference).
#define BB 32
#define TT 4096
#define DD 128
#define CHUNK 64
#define CC (TT / CHUNK)      // 64 chunks per batch
#define NBLK (BB * CC)       // 2048 blocks for phase 1 / 3
#define NAGG (BB * CC * DD)  // 262144 aggregate slots

// Scratch: per-chunk aggregates and resolved incoming states.
// fwd: (last_x, last_t, has, -) ; bwd: (first_x, first_t, has, -)
__device__ float4 g_fwd[NAGG];
__device__ float4 g_bwd[NAGG];
// Incoming state per chunk, defaults already folded in (x_last,t_last)/(x_next,t_next)
__device__ float2 g_pre[NAGG];
__device__ float2 g_suf[NAGG];

// ---------------------------------------------------------------------------
// Phase 1: per-chunk forward aggregate (last observed) and backward aggregate
// (first observed) per channel. One block = (b, chunk), one thread = d.
// Mask arrives as int32 (harness promotes bool -> int32).
// ---------------------------------------------------------------------------
__global__ __launch_bounds__(DD) void phase1(const float* __restrict__ v,
                                             const float* __restrict__ t,
                                             const int* __restrict__ m) {
    int lin = blockIdx.x;          // b*CC + c
    int b = lin / CC, c = lin % CC;
    int d = threadIdx.x;
    int base = (b * TT + c * CHUNK) * DD + d;

    float lx = 0.f, lt = 0.f;      // last observed in chunk
    float fx = 0.f, ft = 0.f;      // first observed in chunk
    float has = 0.f;

#pragma unroll 8
    for (int i = 0; i < CHUNK; i++) {
        int idx = base + i * DD;
        float vv = v[idx];
        float tt = t[idx];
        bool mm = (m[idx] != 0);
        if (mm) {
            if (has == 0.f) { fx = vv; ft = tt; }
            lx = vv; lt = tt; has = 1.f;
        }
    }
    int o = lin * DD + d;
    g_fwd[o] = make_float4(lx, lt, has, 0.f);
    g_bwd[o] = make_float4(fx, ft, has, 0.f);
}

// ---------------------------------------------------------------------------
// Phase 2: cross-chunk exclusive prefix (forward) and exclusive suffix
// (backward) scans per channel. Defaults (x=0, t=times[b,0,d] / times[b,T-1,d])
// are folded so phase 3 needs no has-flags. Grid: B blocks x D threads.
// ---------------------------------------------------------------------------
__global__ __launch_bounds__(DD) void phase2(const float* __restrict__ t) {
    int b = blockIdx.x, d = threadIdx.x;
    float t0   = t[(b * TT) * DD + d];
    float tmax = t[(b * TT + TT - 1) * DD + d];  // times strictly increasing

    float x = 0.f, tc = t0;
    for (int c = 0; c < CC; c++) {
        int o = (b * CC + c) * DD + d;
        g_pre[o] = make_float2(x, tc);
        float4 a = g_fwd[o];
        if (a.z != 0.f) { x = a.x; tc = a.y; }
    }
    x = 0.f; tc = tmax;
    for (int c = CC - 1; c >= 0; c--) {
        int o = (b * CC + c) * DD + d;
        g_suf[o] = make_float2(x, tc);
        float4 a = g_bwd[o];
        if (a.z != 0.f) { x = a.x; tc = a.y; }
    }
}

// ---------------------------------------------------------------------------
// Phase 3: local rescan + interpolation. Forward pass fills per-step
// (x_last, t_last) into smem (thread-private columns, no syncthreads needed),
// backward pass keeps (x_next, t_next) in registers, interpolates, writes.
// Blocks are walked in REVERSE bid order so the re-read hits the data phase 1
// left newest in L2. Output stores use streaming hint to avoid evicting input.
// ---------------------------------------------------------------------------
__global__ __launch_bounds__(DD) void phase3(const float* __restrict__ v,
                                             const float* __restrict__ t,
                                             const int* __restrict__ m,
                                             float* __restrict__ out) {
    extern __shared__ float2 fill[];   // [CHUNK][DD]
    int lin = (NBLK - 1) - blockIdx.x; // reverse order for L2 reuse
    int b = lin / CC, c = lin % CC;
    int d = threadIdx.x;
    int base = (b * TT + c * CHUNK) * DD + d;
    int o = lin * DD + d;

    float2 pre = g_pre[o];
    float xl = pre.x, tl = pre.y;

#pragma unroll 4
    for (int i = 0; i < CHUNK; i++) {
        int idx = base + i * DD;
        float vv = v[idx];
        float tt = t[idx];
        bool mm = (m[idx] != 0);
        if (mm) { xl = vv; tl = tt; }
        fill[i * DD + d] = make_float2(xl, tl);
    }

    float2 suf = g_suf[o];
    float xn = suf.x, tn = suf.y;

#pragma unroll 4
    for (int i = CHUNK - 1; i >= 0; i--) {
        int idx = base + i * DD;
        float vv = v[idx];
        float tt = t[idx];
        bool mm = (m[idx] != 0);
        if (mm) { xn = vv; tn = tt; }
        float2 f = fill[i * DD + d];
        float denom = tn - f.y;
        float num = f.x * (tn - tt) + xn * (tt - f.y);
        float itp = (denom != 0.f) ? (num / denom) : 0.f;
        float res = mm ? vv : itp;
        __stcs(&out[idx], res);    // streaming store: don't evict hot input
    }
}

// ---------------------------------------------------------------------------
extern "C" void kernel_launch(void* const* d_in, const int* in_sizes, int n_in,
                              void* d_out, int out_size) {
    const float* v = (const float*)d_in[0];
    const float* t = (const float*)d_in[1];
    const int*   m = (const int*)d_in[2];
    float* out = (float*)d_out;

    const int smem = CHUNK * DD * (int)sizeof(float2);  // 64 KB
    cudaFuncSetAttribute(phase3, cudaFuncAttributeMaxDynamicSharedMemorySize, smem);

    phase1<<<NBLK, DD>>>(v, t, m);
    phase2<<<BB, DD>>>(t);
    phase3<<<NBLK, DD, smem>>>(v, t, m, out);
}

// round 4
// speedup vs baseline: 2.8367x; 2.8367x over previous
#include <cuda_runtime.h>
#include <cstdint>

// Problem constants (fixed by the reference).
#define BB 32
#define TT 4096
#define DD 128
#define CHUNK 32
#define CC (TT / CHUNK)      // 128 chunks per batch
#define NBLK (BB * CC)       // 4096 chunk-blocks
#define NAGG (NBLK * DD)     // 524288 aggregate slots

// Scratch (static device memory — no allocations).
// fwd: (last_x, last_t, has, -) per chunk; bwd: (first_x, first_t, has, -)
__device__ float4 g_fwd[NAGG];                 // 8 MB
__device__ float4 g_bwd[NAGG];                 // 8 MB
__device__ float2 g_pre[NAGG];                 // 4 MB, incoming fwd state (defaults folded)
__device__ float2 g_suf[NAGG];                 // 4 MB, incoming bwd state (defaults folded)
// Packed mask: 4 words per (b, timestep). Word k, bit l  <->  channel d = 4*l + k.
__device__ unsigned g_mw[BB * TT * 4];         // 2 MB

// ---------------------------------------------------------------------------
// Phase 1: warp-per-chunk, lane handles 4 channels via float4/int4.
// Produces per-chunk fwd/bwd aggregates + packed mask bits.
// ---------------------------------------------------------------------------
__global__ __launch_bounds__(128) void phase1(const float4* __restrict__ v,
                                              const float4* __restrict__ t,
                                              const int4* __restrict__ m) {
    int wid = threadIdx.x >> 5, lane = threadIdx.x & 31;
    int lin = blockIdx.x * 4 + wid;            // chunk id in [0, NBLK)
    int b = lin / CC, c = lin % CC;
    int row0 = b * TT + c * CHUNK;             // first timestep of chunk
    int base4 = row0 * (DD / 4) + lane;        // float4 index

    float lx0=0.f,lx1=0.f,lx2=0.f,lx3=0.f, lt0=0.f,lt1=0.f,lt2=0.f,lt3=0.f;
    float fx0=0.f,fx1=0.f,fx2=0.f,fx3=0.f, ft0=0.f,ft1=0.f,ft2=0.f,ft3=0.f;
    bool h0=false,h1=false,h2=false,h3=false;

#pragma unroll 4
    for (int i = 0; i < CHUNK; i++) {
        float4 v4 = v[base4 + i * (DD / 4)];
        float4 t4 = t[base4 + i * (DD / 4)];
        int4   m4 = m[base4 + i * (DD / 4)];
        bool b0 = (m4.x != 0), b1 = (m4.y != 0), b2 = (m4.z != 0), b3 = (m4.w != 0);
        unsigned w0 = __ballot_sync(0xffffffffu, b0);
        unsigned w1 = __ballot_sync(0xffffffffu, b1);
        unsigned w2 = __ballot_sync(0xffffffffu, b2);
        unsigned w3 = __ballot_sync(0xffffffffu, b3);
        unsigned ws = (lane == 0) ? w0 : (lane == 1) ? w1 : (lane == 2) ? w2 : w3;
        if (lane < 4) g_mw[(row0 + i) * 4 + lane] = ws;

        if (b0) { if (!h0) { fx0 = v4.x; ft0 = t4.x; } lx0 = v4.x; lt0 = t4.x; h0 = true; }
        if (b1) { if (!h1) { fx1 = v4.y; ft1 = t4.y; } lx1 = v4.y; lt1 = t4.y; h1 = true; }
        if (b2) { if (!h2) { fx2 = v4.z; ft2 = t4.z; } lx2 = v4.z; lt2 = t4.z; h2 = true; }
        if (b3) { if (!h3) { fx3 = v4.w; ft3 = t4.w; } lx3 = v4.w; lt3 = t4.w; h3 = true; }
    }

    int o = lin * DD + 4 * lane;
    g_fwd[o + 0] = make_float4(lx0, lt0, h0 ? 1.f : 0.f, 0.f);
    g_fwd[o + 1] = make_float4(lx1, lt1, h1 ? 1.f : 0.f, 0.f);
    g_fwd[o + 2] = make_float4(lx2, lt2, h2 ? 1.f : 0.f, 0.f);
    g_fwd[o + 3] = make_float4(lx3, lt3, h3 ? 1.f : 0.f, 0.f);
    g_bwd[o + 0] = make_float4(fx0, ft0, h0 ? 1.f : 0.f, 0.f);
    g_bwd[o + 1] = make_float4(fx1, ft1, h1 ? 1.f : 0.f, 0.f);
    g_bwd[o + 2] = make_float4(fx2, ft2, h2 ? 1.f : 0.f, 0.f);
    g_bwd[o + 3] = make_float4(fx3, ft3, h3 ? 1.f : 0.f, 0.f);
}

// ---------------------------------------------------------------------------
// Phase 2: cross-chunk exclusive scans. Forward and backward run in separate
// blocks (grid = 2*BB) for 2x parallelism. Defaults (x=0, t=t0 / t=tmax)
// folded in so phase 3 needs no has-flags.
// ---------------------------------------------------------------------------
__global__ __launch_bounds__(DD) void phase2(const float* __restrict__ t) {
    int b = blockIdx.x >> 1, dir = blockIdx.x & 1, d = threadIdx.x;
    if (dir == 0) {
        float x = 0.f, tc = t[(b * TT) * DD + d];            // t0
#pragma unroll 8
        for (int c = 0; c < CC; c++) {
            int o = (b * CC + c) * DD + d;
            float4 a = g_fwd[o];
            g_pre[o] = make_float2(x, tc);
            if (a.z != 0.f) { x = a.x; tc = a.y; }
        }
    } else {
        float x = 0.f, tc = t[(b * TT + TT - 1) * DD + d];   // tmax (cumsum of dt>0)
#pragma unroll 8
        for (int c = CC - 1; c >= 0; c--) {
            int o = (b * CC + c) * DD + d;
            float4 a = g_bwd[o];
            g_suf[o] = make_float2(x, tc);
            if (a.z != 0.f) { x = a.x; tc = a.y; }
        }
    }
}

// ---------------------------------------------------------------------------
// Phase 3: local rescan + interpolation, fill state in registers (no smem).
// Forward pass fills (xl, tl)[i] into fully-unrolled register arrays and packs
// the thread's 32 mask bits into one word; backward pass interpolates and
// writes. Second read of v,t hits L1 (32 KB chunk working set).
// Blocks walked in reverse bid order so early blocks hit the tail phase 1
// left in L2. Streaming stores keep output from evicting hot lines.
// ---------------------------------------------------------------------------
__global__ __launch_bounds__(DD) void phase3(const float* __restrict__ v,
                                             const float* __restrict__ t,
                                             float* __restrict__ out) {
    int lin = (NBLK - 1) - blockIdx.x;         // reverse order for L2 reuse
    int b = lin / CC, c = lin % CC;
    int d = threadIdx.x;
    int row0 = b * TT + c * CHUNK;
    int base = row0 * DD + d;
    int o = lin * DD + d;
    int wsel = (d & 3), bsel = (d >> 2);

    float2 pre = g_pre[o];
    float xl = pre.x, tl = pre.y;
    float fxl[CHUNK], ftl[CHUNK];
    unsigned mbits = 0;

#pragma unroll
    for (int i = 0; i < CHUNK; i++) {
        float vv = v[base + i * DD];
        float tt = t[base + i * DD];
        unsigned w = g_mw[(row0 + i) * 4 + wsel];
        bool mm = (w >> bsel) & 1u;
        mbits |= (mm ? (1u << i) : 0u);
        if (mm) { xl = vv; tl = tt; }
        fxl[i] = xl; ftl[i] = tl;
    }

    float2 suf = g_suf[o];
    float xn = suf.x, tn = suf.y;

#pragma unroll
    for (int i = CHUNK - 1; i >= 0; i--) {
        float vv = v[base + i * DD];           // L1 hit
        float tt = t[base + i * DD];           // L1 hit
        bool mm = (mbits >> i) & 1u;
        if (mm) { xn = vv; tn = tt; }
        float denom = tn - ftl[i];
        float num = fmaf(fxl[i], tn - tt, xn * (tt - ftl[i]));
        float itp = (denom != 0.f) ? (num / denom) : 0.f;
        float res = mm ? vv : itp;
        __stcs(&out[base + i * DD], res);
    }
}

// ---------------------------------------------------------------------------
extern "C" void kernel_launch(void* const* d_in, const int* in_sizes, int n_in,
                              void* d_out, int out_size) {
    const float4* v4 = (const float4*)d_in[0];
    const float4* t4 = (const float4*)d_in[1];
    const int4*   m4 = (const int4*)d_in[2];
    const float*  v  = (const float*)d_in[0];
    const float*  t  = (const float*)d_in[1];
    float* out = (float*)d_out;

    phase1<<<NBLK / 4, 128>>>(v4, t4, m4);
    phase2<<<BB * 2, DD>>>(t);
    phase3<<<NBLK, DD>>>(v, t, out);
}

// round 5
// speedup vs baseline: 3.0913x; 1.0897x over previous
#include <cuda_runtime.h>
#include <cstdint>

// Problem constants (fixed by the reference).
#define BB 32
#define TT 4096
#define DD 128
#define CHUNK 32
#define CC (TT / CHUNK)      // 128 chunks per batch
#define NBLK (BB * CC)       // 4096 chunk-blocks
#define NAGG (NBLK * DD)     // 524288 aggregate slots

// Scratch (static device memory — no allocations).
// fwd: (last_x, last_t, has, -) per chunk; bwd: (first_x, first_t, has, -)
__device__ float4 g_fwd[NAGG];                 // 8 MB
__device__ float4 g_bwd[NAGG];                 // 8 MB
__device__ float2 g_pre[NAGG];                 // 4 MB, incoming fwd state (defaults folded)
__device__ float2 g_suf[NAGG];                 // 4 MB, incoming bwd state (defaults folded)
// Packed mask: 4 words per (b, timestep). Word k, bit l  <->  channel d = 4*l + k.
__device__ unsigned g_mw[BB * TT * 4];         // 2 MB

// ---------------------------------------------------------------------------
// Phase 1: warp-per-chunk, lane handles 4 channels via float4/int4.
// Produces per-chunk fwd/bwd aggregates + packed mask bits.
// ---------------------------------------------------------------------------
__global__ __launch_bounds__(128) void phase1(const float4* __restrict__ v,
                                              const float4* __restrict__ t,
                                              const int4* __restrict__ m) {
    int wid = threadIdx.x >> 5, lane = threadIdx.x & 31;
    int lin = blockIdx.x * 4 + wid;            // chunk id in [0, NBLK)
    int b = lin / CC, c = lin % CC;
    int row0 = b * TT + c * CHUNK;             // first timestep of chunk
    int base4 = row0 * (DD / 4) + lane;        // float4 index

    float lx0=0.f,lx1=0.f,lx2=0.f,lx3=0.f, lt0=0.f,lt1=0.f,lt2=0.f,lt3=0.f;
    float fx0=0.f,fx1=0.f,fx2=0.f,fx3=0.f, ft0=0.f,ft1=0.f,ft2=0.f,ft3=0.f;
    bool h0=false,h1=false,h2=false,h3=false;

#pragma unroll 4
    for (int i = 0; i < CHUNK; i++) {
        float4 v4 = v[base4 + i * (DD / 4)];
        float4 t4 = t[base4 + i * (DD / 4)];
        int4   m4 = m[base4 + i * (DD / 4)];
        bool b0 = (m4.x != 0), b1 = (m4.y != 0), b2 = (m4.z != 0), b3 = (m4.w != 0);
        unsigned w0 = __ballot_sync(0xffffffffu, b0);
        unsigned w1 = __ballot_sync(0xffffffffu, b1);
        unsigned w2 = __ballot_sync(0xffffffffu, b2);
        unsigned w3 = __ballot_sync(0xffffffffu, b3);
        unsigned ws = (lane == 0) ? w0 : (lane == 1) ? w1 : (lane == 2) ? w2 : w3;
        if (lane < 4) g_mw[(row0 + i) * 4 + lane] = ws;

        if (b0) { if (!h0) { fx0 = v4.x; ft0 = t4.x; } lx0 = v4.x; lt0 = t4.x; h0 = true; }
        if (b1) { if (!h1) { fx1 = v4.y; ft1 = t4.y; } lx1 = v4.y; lt1 = t4.y; h1 = true; }
        if (b2) { if (!h2) { fx2 = v4.z; ft2 = t4.z; } lx2 = v4.z; lt2 = t4.z; h2 = true; }
        if (b3) { if (!h3) { fx3 = v4.w; ft3 = t4.w; } lx3 = v4.w; lt3 = t4.w; h3 = true; }
    }

    int o = lin * DD + 4 * lane;
    g_fwd[o + 0] = make_float4(lx0, lt0, h0 ? 1.f : 0.f, 0.f);
    g_fwd[o + 1] = make_float4(lx1, lt1, h1 ? 1.f : 0.f, 0.f);
    g_fwd[o + 2] = make_float4(lx2, lt2, h2 ? 1.f : 0.f, 0.f);
    g_fwd[o + 3] = make_float4(lx3, lt3, h3 ? 1.f : 0.f, 0.f);
    g_bwd[o + 0] = make_float4(fx0, ft0, h0 ? 1.f : 0.f, 0.f);
    g_bwd[o + 1] = make_float4(fx1, ft1, h1 ? 1.f : 0.f, 0.f);
    g_bwd[o + 2] = make_float4(fx2, ft2, h2 ? 1.f : 0.f, 0.f);
    g_bwd[o + 3] = make_float4(fx3, ft3, h3 ? 1.f : 0.f, 0.f);
}

// ---------------------------------------------------------------------------
// Phase 2: cross-chunk exclusive scans, warp-parallel.
// One warp per (batch, channel, direction): 8192 warps total. Each lane folds
// 4 chunk aggregates, 5-step shfl_up inclusive scan (combine = right if
// right.has else left), shift to exclusive, fold the default seed
// (x=0, t=t0 or t_max, has=1), then replay writing exclusive states.
// ---------------------------------------------------------------------------
__global__ __launch_bounds__(256) void phase2(const float* __restrict__ t) {
    int gw = (blockIdx.x * blockDim.x + threadIdx.x) >> 5;   // global warp id
    int lane = threadIdx.x & 31;
    int dir = gw & 1;
    int pair = gw >> 1;                 // [0, BB*DD)
    int b = pair / DD, d = pair % DD;

    const float4* agg = dir ? g_bwd : g_fwd;
    float2* outp      = dir ? g_suf : g_pre;
    float seed_t = dir ? t[(b * TT + TT - 1) * DD + d]       // t_max (cumsum, dt>0)
                       : t[(b * TT) * DD + d];               // t0

    // Load this lane's 4 aggregates along the scan direction.
    float4 a[4];
    int cbase = lane * 4;
#pragma unroll
    for (int j = 0; j < 4; j++) {
        int rc = cbase + j;
        int c = dir ? (CC - 1 - rc) : rc;
        a[j] = agg[(b * CC + c) * DD + d];
    }

    // Lane-local inclusive aggregate.
    float x = 0.f, tc = 0.f; int h = 0;
#pragma unroll
    for (int j = 0; j < 4; j++)
        if (a[j].z != 0.f) { x = a[j].x; tc = a[j].y; h = 1; }

    // Warp inclusive scan.
#pragma unroll
    for (int off = 1; off < 32; off <<= 1) {
        float px = __shfl_up_sync(0xffffffffu, x, off);
        float pt = __shfl_up_sync(0xffffffffu, tc, off);
        int   ph = __shfl_up_sync(0xffffffffu, h, off);
        if (lane >= off && !h) { x = px; tc = pt; h = ph; }
    }

    // Exclusive = shift by 1; fold default seed where nothing observed yet.
    float ex = __shfl_up_sync(0xffffffffu, x, 1);
    float et = __shfl_up_sync(0xffffffffu, tc, 1);
    int   eh = __shfl_up_sync(0xffffffffu, h, 1);
    if (lane == 0 || !eh) { ex = 0.f; et = seed_t; }

    // Replay: write exclusive state per chunk, then fold that chunk in.
    float sx = ex, st = et;
#pragma unroll
    for (int j = 0; j < 4; j++) {
        int rc = cbase + j;
        int c = dir ? (CC - 1 - rc) : rc;
        outp[(b * CC + c) * DD + d] = make_float2(sx, st);
        if (a[j].z != 0.f) { sx = a[j].x; st = a[j].y; }
    }
}

// ---------------------------------------------------------------------------
// Phase 3: local rescan + interpolation, fill state in registers (no smem).
// Forward pass fills (xl, tl)[i] into fully-unrolled register arrays and packs
// the thread's 32 mask bits into one word; backward pass interpolates and
// writes. Second read of v,t hits L1 (32 KB chunk working set).
// Blocks walked in reverse bid order so early blocks hit the tail phase 1
// left in L2. Streaming stores keep output from evicting hot lines.
// ---------------------------------------------------------------------------
__global__ __launch_bounds__(DD) void phase3(const float* __restrict__ v,
                                             const float* __restrict__ t,
                                             float* __restrict__ out) {
    int lin = (NBLK - 1) - blockIdx.x;         // reverse order for L2 reuse
    int b = lin / CC, c = lin % CC;
    int d = threadIdx.x;
    int row0 = b * TT + c * CHUNK;
    int base = row0 * DD + d;
    int o = lin * DD + d;
    int wsel = (d & 3), bsel = (d >> 2);

    float2 pre = g_pre[o];
    float xl = pre.x, tl = pre.y;
    float fxl[CHUNK], ftl[CHUNK];
    unsigned mbits = 0;

#pragma unroll
    for (int i = 0; i < CHUNK; i++) {
        float vv = v[base + i * DD];
        float tt = t[base + i * DD];
        unsigned w = g_mw[(row0 + i) * 4 + wsel];
        bool mm = (w >> bsel) & 1u;
        mbits |= (mm ? (1u << i) : 0u);
        if (mm) { xl = vv; tl = tt; }
        fxl[i] = xl; ftl[i] = tl;
    }

    float2 suf = g_suf[o];
    float xn = suf.x, tn = suf.y;

#pragma unroll
    for (int i = CHUNK - 1; i >= 0; i--) {
        float vv = v[base + i * DD];           // L1 hit
        float tt = t[base + i * DD];           // L1 hit
        bool mm = (mbits >> i) & 1u;
        if (mm) { xn = vv; tn = tt; }
        float denom = tn - ftl[i];
        float num = fmaf(fxl[i], tn - tt, xn * (tt - ftl[i]));
        float itp = (denom != 0.f) ? (num / denom) : 0.f;
        float res = mm ? vv : itp;
        __stcs(&out[base + i * DD], res);
    }
}

// ---------------------------------------------------------------------------
extern "C" void kernel_launch(void* const* d_in, const int* in_sizes, int n_in,
                              void* d_out, int out_size) {
    const float4* v4 = (const float4*)d_in[0];
    const float4* t4 = (const float4*)d_in[1];
    const int4*   m4 = (const int4*)d_in[2];
    const float*  v  = (const float*)d_in[0];
    const float*  t  = (const float*)d_in[1];
    float* out = (float*)d_out;

    phase1<<<NBLK / 4, 128>>>(v4, t4, m4);
    phase2<<<(2 * BB * DD * 32) / 256, 256>>>(t);
    phase3<<<NBLK, DD>>>(v, t, out);
}